// round 1
// baseline (speedup 1.0000x reference)
#include <cuda_runtime.h>

// ---------------------------------------------------------------------------
// StyledLayer: bilinear 2x upsample -> style linear -> modulated 3x3 conv
//              -> demodulate -> noise inject -> leaky_relu * sqrt(2)
//
// Shapes: x[16,512,32,32], w[16,512], noise[16,1,64,64], lin_w[512,512],
//         lin_b[512], conv_w[512,512,3,3], noise_weight scalar.
// Output: [16,512,64,64] fp32.
// ---------------------------------------------------------------------------

#define BATCH 16
#define CIN   512
#define COUT  512
#define SDIM  512
#define HIN   32
#define WIN   32
#define HOUT  64
#define WOUT  64
#define NPIX  (HOUT * WOUT)          // 4096

#define LIN_SCALE  0.044194173824159216f   // 1/sqrt(512)
#define CONV_SCALE 0.014731391274719738f   // 1/sqrt(512*9)
#define ACT_GAIN   1.4142135623730951f
#define NEG_SLOPE  0.2f
#define DEMOD_EPS  1e-8f

// Scratch (device globals: allocation-free per harness rules)
__device__ float g_xm[BATCH * CIN * NPIX];      // modulated upsampled input (134 MB)
__device__ float g_wT[9 * CIN * COUT];          // wT[pos][cin][cout], CONV_SCALE folded
__device__ float g_wsq[CIN * COUT];             // wsq[cin][cout] = sum_pos wk^2
__device__ float g_s[BATCH * CIN];              // style
__device__ float g_demod[BATCH * COUT];         // demod coefficients

// ---------------------------------------------------------------------------
// 1) style: s[b,c] = LIN_SCALE * dot(w[b,:], lin_w[c,:]) + lin_b[c]
// ---------------------------------------------------------------------------
__global__ void style_k(const float* __restrict__ w,
                        const float* __restrict__ lin_w,
                        const float* __restrict__ lin_b) {
    int b = blockIdx.x;
    int c = threadIdx.x;                 // 512 threads
    __shared__ float ws[SDIM];
    ws[c] = w[b * SDIM + c];
    __syncthreads();
    const float* row = lin_w + (size_t)c * SDIM;
    float acc = 0.f;
#pragma unroll 8
    for (int i = 0; i < SDIM; i++) acc += ws[i] * row[i];
    g_s[b * CIN + c] = acc * LIN_SCALE + lin_b[c];
}

// ---------------------------------------------------------------------------
// 2) weight prep: wT[pos][cin][cout] = conv_w[cout][cin][pos] * CONV_SCALE
//    wsq[cin][cout] = sum_pos wT^2
// ---------------------------------------------------------------------------
__global__ void wprep_k(const float* __restrict__ conv_w) {
    int idx = blockIdx.x * blockDim.x + threadIdx.x;   // COUT*CIN
    if (idx >= COUT * CIN) return;
    int o = idx & (COUT - 1);
    int i = idx >> 9;
    const float* src = conv_w + ((size_t)o * CIN + i) * 9;
    float sq = 0.f;
#pragma unroll
    for (int p = 0; p < 9; p++) {
        float v = src[p] * CONV_SCALE;
        g_wT[(size_t)p * CIN * COUT + (size_t)i * COUT + o] = v;
        sq += v * v;
    }
    g_wsq[(size_t)i * COUT + o] = sq;
}

// ---------------------------------------------------------------------------
// 3) demod[b,o] = rsqrt( sum_i s[b,i]^2 * wsq[i][o] + eps )
// ---------------------------------------------------------------------------
__global__ void demod_k() {
    int b = blockIdx.x;
    int o = threadIdx.x;                 // 512 threads
    __shared__ float s2[CIN];
    float sv = g_s[b * CIN + o];
    s2[o] = sv * sv;
    __syncthreads();
    float acc = 0.f;
#pragma unroll 8
    for (int i = 0; i < CIN; i++) acc += s2[i] * g_wsq[(size_t)i * COUT + o];
    g_demod[b * COUT + o] = rsqrtf(acc + DEMOD_EPS);
}

// ---------------------------------------------------------------------------
// 4) upsample (half-pixel bilinear 2x, edge clamped) + style modulation
//    xm[b,c,y,x] = s[b,c] * bilinear(x_in)
// ---------------------------------------------------------------------------
__global__ void upmod_k(const float* __restrict__ x) {
    int idx = blockIdx.x * blockDim.x + threadIdx.x;
    if (idx >= BATCH * CIN * NPIX) return;
    int px = idx & 63;
    int py = (idx >> 6) & 63;
    int c  = (idx >> 12) & 511;
    int b  = idx >> 21;

    // src coord = out/2 - 0.25; floor/frac by parity
    int fy = (py - 1) >> 1;              // arithmetic shift: py=0 -> -1
    int fx = (px - 1) >> 1;
    float fr_y = (py & 1) ? 0.25f : 0.75f;
    float fr_x = (px & 1) ? 0.25f : 0.75f;
    int y0 = max(fy, 0), y1 = min(fy + 1, HIN - 1);
    int x0 = max(fx, 0), x1 = min(fx + 1, WIN - 1);

    const float* xp = x + ((size_t)(b * CIN + c)) * (HIN * WIN);
    float v00 = xp[y0 * WIN + x0];
    float v01 = xp[y0 * WIN + x1];
    float v10 = xp[y1 * WIN + x0];
    float v11 = xp[y1 * WIN + x1];
    float wy0 = 1.f - fr_y, wx0 = 1.f - fr_x;
    float val = wy0 * (wx0 * v00 + fr_x * v01) + fr_y * (wx0 * v10 + fr_x * v11);
    g_xm[idx] = g_s[b * CIN + c] * val;
}

// ---------------------------------------------------------------------------
// 5) conv as implicit GEMM per batch:
//    out[b, m, n] = sum_{pos, cin} wT[pos][cin][m] * xm[b][cin][pix(n)+off(pos)]
//    M=512, N=4096, K=4608. Tiles BM=BN=128, BK=16, 256 threads, 8x8 micro.
//    Fused epilogue: *demod + noise_weight*noise, leaky_relu*sqrt(2).
// ---------------------------------------------------------------------------
#define BM  128
#define BN  128
#define BKc 16

__global__ void __launch_bounds__(256)
conv_k(const float* __restrict__ noise,
       const float* __restrict__ nwp,
       float* __restrict__ out) {
    __shared__ float As[BKc][BM];
    __shared__ float Bs[BKc][BN];

    int b  = blockIdx.z;
    int m0 = blockIdx.y * BM;
    int n0 = blockIdx.x * BN;
    int tid = threadIdx.x;
    int tx = tid & 15;
    int ty = tid >> 4;

    // B-tile load mapping: each thread owns pixel column n, rows kk = 2e+hi
    int n  = tid & 127;
    int hi = tid >> 7;                   // 0/1
    int gn = n0 + n;
    int py = gn >> 6;
    int px = gn & 63;

    // A-tile load mapping: float4 along cout
    int m4 = (tid & 31) * 4;
    int ka = tid >> 5;                   // 0..7

    float acc[8][8];
#pragma unroll
    for (int i = 0; i < 8; i++)
#pragma unroll
        for (int j = 0; j < 8; j++) acc[i][j] = 0.f;

    const float* xb = g_xm + (size_t)b * CIN * NPIX;

    for (int pos = 0; pos < 9; pos++) {
        int dy = pos / 3;
        int dx = pos - dy * 3;
        int sy = py + dy - 1;
        int sx = px + dx - 1;
        bool valid = (sy >= 0) & (sy < HOUT) & (sx >= 0) & (sx < WOUT);
        const float* bp = xb + (valid ? (sy * WOUT + sx) : 0);
        const float* ap = g_wT + (size_t)pos * CIN * COUT + m0 + m4;

        for (int cc = 0; cc < 32; cc++) {
            int cinb = cc * 16;
            // load A tile: 2 x float4 per thread (coalesced; wT row-major in cout)
#pragma unroll
            for (int e = 0; e < 2; e++) {
                int kk = e * 8 + ka;
                float4 v = *(const float4*)(ap + (size_t)(cinb + kk) * COUT);
                *(float4*)&As[kk][m4] = v;
            }
            // load B tile: 8 scalars per thread (zero-padded halo)
#pragma unroll
            for (int e = 0; e < 8; e++) {
                int kk = e * 2 + hi;
                float v = valid ? bp[(size_t)(cinb + kk) * NPIX] : 0.f;
                Bs[kk][n] = v;
            }
            __syncthreads();

#pragma unroll
            for (int kk = 0; kk < BKc; kk++) {
                float a[8], bb[8];
                *(float4*)&a[0]  = *(const float4*)&As[kk][ty * 4];
                *(float4*)&a[4]  = *(const float4*)&As[kk][64 + ty * 4];
                *(float4*)&bb[0] = *(const float4*)&Bs[kk][tx * 4];
                *(float4*)&bb[4] = *(const float4*)&Bs[kk][64 + tx * 4];
#pragma unroll
                for (int i = 0; i < 8; i++)
#pragma unroll
                    for (int j = 0; j < 8; j++)
                        acc[i][j] += a[i] * bb[j];
            }
            __syncthreads();
        }
    }

    // Epilogue: demod, noise, leaky relu, gain; float4 coalesced stores
    float nw = *nwp;
    const float* nrow = noise + (size_t)b * NPIX;
#pragma unroll
    for (int i = 0; i < 8; i++) {
        int gm = m0 + ty * 4 + ((i < 4) ? i : 60 + i);   // rows {ty*4+i} U {64+ty*4+(i-4)}
        float dm = g_demod[b * COUT + gm];
        float* orow = out + ((size_t)(b * COUT + gm)) * NPIX;
#pragma unroll
        for (int jh = 0; jh < 2; jh++) {
            int base = n0 + jh * 64 + tx * 4;
            float4 v;
            float* vp = (float*)&v;
#pragma unroll
            for (int q = 0; q < 4; q++) {
                float val = acc[i][jh * 4 + q] * dm + nw * nrow[base + q];
                val = (val >= 0.f ? val : NEG_SLOPE * val) * ACT_GAIN;
                vp[q] = val;
            }
            *(float4*)(orow + base) = v;
        }
    }
}

// ---------------------------------------------------------------------------
extern "C" void kernel_launch(void* const* d_in, const int* in_sizes, int n_in,
                              void* d_out, int out_size) {
    const float* x      = (const float*)d_in[0];   // [16,512,32,32]
    const float* w      = (const float*)d_in[1];   // [16,512]
    const float* noise  = (const float*)d_in[2];   // [16,1,64,64]
    const float* lin_w  = (const float*)d_in[3];   // [512,512]
    const float* lin_b  = (const float*)d_in[4];   // [512]
    const float* conv_w = (const float*)d_in[5];   // [512,512,3,3]
    const float* nwp    = (const float*)d_in[6];   // scalar
    float* out = (float*)d_out;                    // [16,512,64,64]

    style_k<<<BATCH, 512>>>(w, lin_w, lin_b);
    wprep_k<<<(COUT * CIN + 255) / 256, 256>>>(conv_w);
    demod_k<<<BATCH, 512>>>();
    upmod_k<<<(BATCH * CIN * NPIX + 255) / 256, 256>>>(x);

    dim3 grid(NPIX / BN, COUT / BM, BATCH);        // (32, 4, 16)
    conv_k<<<grid, 256>>>(noise, nwp, out);
}

// round 6
// speedup vs baseline: 1.9228x; 1.9228x over previous
#include <cuda_runtime.h>
#include <cstdint>

// ---------------------------------------------------------------------------
// StyledLayer (sm_100 plain-target safe): bilinear 2x up -> style ->
// modulated 3x3 conv as TF32 mma.sync implicit GEMM -> demod -> noise ->
// leaky_relu * sqrt(2).   No tcgen05 (ptxas target lacks the 'a' suffix).
// ---------------------------------------------------------------------------

#define BATCH 16
#define CIN   512
#define COUT  512
#define SDIM  512
#define HIN   32
#define WIN   32
#define NPIX  4096
#define KTOT  4608              // 9 * 512

#define LIN_SCALE  0.044194173824159216f
#define CONV_SCALE 0.014731391274719738f
#define ACT_GAIN   1.4142135623730951f
#define NEG_SLOPE  0.2f
#define DEMOD_EPS  1e-8f

// GEMM tiling
#define BM 128
#define BN 256
#define BK 16
#define NCHUNK 288              // KTOT / BK
#define RPAD 20                 // floats per smem row (80B, conflict-free)
#define A_BYTES (BM * RPAD * 4) // 10240
#define B_BYTES (BN * RPAD * 4) // 20480
#define STAGE_BYTES (A_BYTES + B_BYTES)   // 30720
#define NSTAGE 3
#define SMEM_CONV (NSTAGE * STAGE_BYTES)  // 92160

// scratch
__device__ float g_xt[BATCH * NPIX * CIN];   // [b][pix][ci], tf32-rounded, modulated
__device__ float g_wK[COUT * KTOT];          // [cout][pos*512+ci], tf32, scaled
__device__ float g_wsq[CIN * COUT];
__device__ float g_s[BATCH * CIN];
__device__ float g_demod[BATCH * COUT];

// ---------------------------------------------------------------------------
// PTX helpers (all legal on plain sm_100: sm_80-era instructions)
// ---------------------------------------------------------------------------
__device__ __forceinline__ uint32_t smem_u32(const void* p) {
    uint32_t a;
    asm("{ .reg .u64 t; cvta.to.shared.u64 t, %1; cvt.u32.u64 %0, t; }"
        : "=r"(a) : "l"(p));
    return a;
}

// cvt.rna.tf32.f32 requires a b32 destination register
__device__ __forceinline__ float to_tf32(float v) {
    uint32_t u;
    asm("cvt.rna.tf32.f32 %0, %1;" : "=r"(u) : "f"(v));
    return __uint_as_float(u);
}

__device__ __forceinline__ void cp16(uint32_t dst, const void* src, int sz) {
    asm volatile("cp.async.cg.shared.global [%0], [%1], 16, %2;"
                 :: "r"(dst), "l"(src), "r"(sz));
}

#define CP_COMMIT() asm volatile("cp.async.commit_group;" ::: "memory")
#define CP_WAIT1()  asm volatile("cp.async.wait_group 1;" ::: "memory")
#define CP_WAIT0()  asm volatile("cp.async.wait_group 0;" ::: "memory")

__device__ __forceinline__ void ldsm4(uint32_t* r, uint32_t addr) {
    asm volatile("ldmatrix.sync.aligned.m8n8.x4.shared.b16 {%0,%1,%2,%3}, [%4];"
                 : "=r"(r[0]), "=r"(r[1]), "=r"(r[2]), "=r"(r[3]) : "r"(addr));
}

__device__ __forceinline__ void mma8(float* d, const uint32_t* a, const uint32_t* b) {
    asm volatile(
        "mma.sync.aligned.m16n8k8.row.col.f32.tf32.tf32.f32 "
        "{%0,%1,%2,%3}, {%4,%5,%6,%7}, {%8,%9}, {%0,%1,%2,%3};"
        : "+f"(d[0]), "+f"(d[1]), "+f"(d[2]), "+f"(d[3])
        : "r"(a[0]), "r"(a[1]), "r"(a[2]), "r"(a[3]), "r"(b[0]), "r"(b[1]));
}

// ---------------------------------------------------------------------------
// prep kernels
// ---------------------------------------------------------------------------
__global__ void style_k(const float* __restrict__ w,
                        const float* __restrict__ lin_w,
                        const float* __restrict__ lin_b) {
    int b = blockIdx.x;
    int c = threadIdx.x;
    __shared__ float ws[SDIM];
    ws[c] = w[b * SDIM + c];
    __syncthreads();
    const float* row = lin_w + (size_t)c * SDIM;
    float acc = 0.f;
#pragma unroll 8
    for (int i = 0; i < SDIM; i++) acc += ws[i] * row[i];
    g_s[b * CIN + c] = acc * LIN_SCALE + lin_b[c];
}

// g_wK[o][pos*512+ci] = tf32(conv_w[o][ci][pos] * CONV_SCALE)
__global__ void wk_k(const float* __restrict__ conv_w) {
    int idx = blockIdx.x * 256 + threadIdx.x;
    if (idx >= COUT * CIN) return;
    int ci = idx & 511;
    int o  = idx >> 9;
    const float* src = conv_w + ((size_t)o * CIN + ci) * 9;
    float* dst = g_wK + (size_t)o * KTOT + ci;
#pragma unroll
    for (int p = 0; p < 9; p++)
        dst[p * 512] = to_tf32(src[p] * CONV_SCALE);
}

__global__ void wsq_k(const float* __restrict__ conv_w) {
    int idx = blockIdx.x * 256 + threadIdx.x;
    if (idx >= COUT * CIN) return;
    int o = idx & 511;
    int i = idx >> 9;
    const float* src = conv_w + ((size_t)o * CIN + i) * 9;
    float sq = 0.f;
#pragma unroll
    for (int p = 0; p < 9; p++) {
        float v = src[p] * CONV_SCALE;
        sq += v * v;
    }
    g_wsq[(size_t)i * COUT + o] = sq;
}

__global__ void demod_k() {
    int b = blockIdx.x;
    int o = threadIdx.x;
    __shared__ float s2[CIN];
    float sv = g_s[b * CIN + o];
    s2[o] = sv * sv;
    __syncthreads();
    float acc = 0.f;
#pragma unroll 8
    for (int i = 0; i < CIN; i++) acc += s2[i] * g_wsq[(size_t)i * COUT + o];
    g_demod[b * COUT + o] = rsqrtf(acc + DEMOD_EPS);
}

// ---------------------------------------------------------------------------
// upsample + modulate + transpose: g_xt[b][pix][ci], tf32-rounded
// ---------------------------------------------------------------------------
__global__ void __launch_bounds__(256) xt_k(const float* __restrict__ x) {
    extern __shared__ float sm[];          // [32][1025]
    int b  = blockIdx.x >> 4;
    int cb = blockIdx.x & 15;
    int ci0 = cb * 32;
    int tid = threadIdx.x;

    const float* xb = x + ((size_t)(b * CIN + ci0)) * (HIN * WIN);
#pragma unroll
    for (int i = 0; i < 32; i++)
        for (int j = tid; j < 1024; j += 256)
            sm[i * 1025 + j] = xb[(size_t)i * 1024 + j];
    __syncthreads();

    int c  = tid & 31;
    int pg = tid >> 5;
    float sv = g_s[b * CIN + ci0 + c];
    float* dst = g_xt + (size_t)b * NPIX * CIN + ci0 + c;
    const float* row = sm + c * 1025;

    for (int e = 0; e < 512; e++) {
        int p  = pg + (e << 3);
        int py = p >> 6, px = p & 63;
        int fy = (py - 1) >> 1;
        int fx = (px - 1) >> 1;
        float ay = (py & 1) ? 0.25f : 0.75f;
        float ax = (px & 1) ? 0.25f : 0.75f;
        int y0 = max(fy, 0), y1 = min(fy + 1, HIN - 1);
        int x0 = max(fx, 0), x1 = min(fx + 1, WIN - 1);
        float v00 = row[y0 * WIN + x0];
        float v01 = row[y0 * WIN + x1];
        float v10 = row[y1 * WIN + x0];
        float v11 = row[y1 * WIN + x1];
        float val = (1.f - ay) * ((1.f - ax) * v00 + ax * v01)
                  +        ay  * ((1.f - ax) * v10 + ax * v11);
        dst[(size_t)p * CIN] = to_tf32(sv * val);
    }
}

// ---------------------------------------------------------------------------
// conv: TF32 mma.sync implicit GEMM.
// CTA tile 128(cout) x 256(pix), K in chunks of 16 (288 chunks over 9 pos).
// smem stage: As[128][20] + Bs[256][20] (80B rows, conflict-free ldmatrix).
// ---------------------------------------------------------------------------
__global__ void __launch_bounds__(256, 1)
conv_mma_k(const float* __restrict__ noise,
           const float* __restrict__ nwp,
           float* __restrict__ out) {
    extern __shared__ char smem[];
    uint32_t sb = smem_u32(smem);

    int tid  = threadIdx.x;
    int lane = tid & 31;
    int wid  = tid >> 5;
    int wm   = (wid & 1) * 64;          // warp m offset
    int wn   = (wid >> 1) * 64;         // warp n offset

    int b  = blockIdx.z;
    int m0 = blockIdx.y * BM;
    int n0 = blockIdx.x * BN;
    int py0 = n0 >> 6;                  // 4 rows of 64 pixels per CTA

    const float* xtb = g_xt + (size_t)b * NPIX * CIN;

    // ---- per-thread cp.async source/dest mapping ----
    // A: 2 chunks of 16B; idx = tid*2+e2 -> m = idx>>2, e = idx&3
    int am[2], ae[2];
    uint32_t adst[2];
#pragma unroll
    for (int e2 = 0; e2 < 2; e2++) {
        int idx = tid * 2 + e2;
        am[e2] = idx >> 2;
        ae[e2] = idx & 3;
        adst[e2] = am[e2] * (RPAD * 4) + ae[e2] * 16;
    }
    // B: pixel n = tid, 4 chunks of 16B
    int npix_loc = tid;
    int brow = npix_loc >> 6;           // 0..3
    int bcol = npix_loc & 63;
    uint32_t bdst0 = A_BYTES + npix_loc * (RPAD * 4);

    // ---- per-thread ldmatrix address offsets ----
    int g = lane >> 3, r = lane & 7;
    uint32_t aoff = (uint32_t)((wm + (g & 1) * 8 + r) * (RPAD * 4) + (g >> 1) * 16);
    uint32_t boff = (uint32_t)(A_BYTES + (wn + (g >> 1) * 8 + r) * (RPAD * 4) + (g & 1) * 16);

    float acc[4][8][4];
#pragma unroll
    for (int i = 0; i < 4; i++)
#pragma unroll
        for (int j = 0; j < 8; j++)
#pragma unroll
            for (int q = 0; q < 4; q++) acc[i][j][q] = 0.f;

    // ---- chunk loader ----
    auto load_chunk = [&](int c, int st) {
        int pos = c >> 5;
        int ci0 = (c & 31) << 4;
        int dy = pos / 3 - 1, dx = pos % 3 - 1;
        int kbase = pos * 512 + ci0;
        uint32_t stb = sb + st * STAGE_BYTES;
#pragma unroll
        for (int e2 = 0; e2 < 2; e2++) {
            const float* src = g_wK + (size_t)(m0 + am[e2]) * KTOT + kbase + ae[e2] * 4;
            cp16(stb + adst[e2], src, 16);
        }
        int py = py0 + brow + dy;
        int px = bcol + dx;
        bool v = ((unsigned)py < 64u) && ((unsigned)px < 64u);
        const float* bsrc = xtb + ((size_t)(v ? (py * 64 + px) : 0) * CIN) + ci0;
        int sz = v ? 16 : 0;
#pragma unroll
        for (int e = 0; e < 4; e++)
            cp16(stb + bdst0 + e * 16, bsrc + e * 4, sz);
        CP_COMMIT();
    };

    load_chunk(0, 0);
    load_chunk(1, 1);

    for (int c = 0; c < NCHUNK; c++) {
        int s = c % NSTAGE;
        if (c + 1 < NCHUNK) { CP_WAIT1(); } else { CP_WAIT0(); }
        __syncthreads();

        if (c + 2 < NCHUNK) load_chunk(c + 2, (c + 2) % NSTAGE);

        uint32_t stb = sb + s * STAGE_BYTES;
#pragma unroll
        for (int ks = 0; ks < 2; ks++) {
            uint32_t af[4][4], bf[4][4];
#pragma unroll
            for (int mt = 0; mt < 4; mt++)
                ldsm4(af[mt], stb + aoff + mt * (16 * RPAD * 4) + ks * 32);
#pragma unroll
            for (int j = 0; j < 4; j++)
                ldsm4(bf[j], stb + boff + j * (16 * RPAD * 4) + ks * 32);
#pragma unroll
            for (int mt = 0; mt < 4; mt++)
#pragma unroll
                for (int nt = 0; nt < 8; nt++)
                    mma8(acc[mt][nt], af[mt], &bf[nt >> 1][(nt & 1) * 2]);
        }
    }

    // ---- epilogue: demod + noise + lrelu*gain, float2 stores ----
    float nw = *nwp;
    const float* nb = noise + (size_t)b * NPIX;
#pragma unroll
    for (int mt = 0; mt < 4; mt++) {
        int rbase = m0 + wm + mt * 16 + (lane >> 2);
#pragma unroll
        for (int half = 0; half < 2; half++) {
            int cout = rbase + half * 8;
            float dm = g_demod[b * COUT + cout];
            float* orow = out + ((size_t)(b * COUT + cout)) * NPIX;
#pragma unroll
            for (int nt = 0; nt < 8; nt++) {
                int pix = n0 + wn + nt * 8 + 2 * (lane & 3);
                float v0 = acc[mt][nt][half * 2 + 0] * dm + nw * nb[pix];
                float v1 = acc[mt][nt][half * 2 + 1] * dm + nw * nb[pix + 1];
                v0 = (v0 >= 0.f ? v0 : NEG_SLOPE * v0) * ACT_GAIN;
                v1 = (v1 >= 0.f ? v1 : NEG_SLOPE * v1) * ACT_GAIN;
                float2 o2 = make_float2(v0, v1);
                *(float2*)(orow + pix) = o2;
            }
        }
    }
}

// ---------------------------------------------------------------------------
extern "C" void kernel_launch(void* const* d_in, const int* in_sizes, int n_in,
                              void* d_out, int out_size) {
    const float* x      = (const float*)d_in[0];
    const float* w      = (const float*)d_in[1];
    const float* noise  = (const float*)d_in[2];
    const float* lin_w  = (const float*)d_in[3];
    const float* lin_b  = (const float*)d_in[4];
    const float* conv_w = (const float*)d_in[5];
    const float* nwp    = (const float*)d_in[6];
    float* out = (float*)d_out;

    cudaFuncSetAttribute(xt_k, cudaFuncAttributeMaxDynamicSharedMemorySize, 32 * 1025 * 4);
    cudaFuncSetAttribute(conv_mma_k, cudaFuncAttributeMaxDynamicSharedMemorySize, SMEM_CONV);

    style_k<<<BATCH, 512>>>(w, lin_w, lin_b);
    wk_k<<<(COUT * CIN + 255) / 256, 256>>>(conv_w);
    wsq_k<<<(COUT * CIN + 255) / 256, 256>>>(conv_w);
    demod_k<<<BATCH, 512>>>();
    xt_k<<<BATCH * 16, 256, 32 * 1025 * 4>>>(x);

    dim3 grid(NPIX / BN, COUT / BM, BATCH);   // (16, 4, 16)
    conv_mma_k<<<grid, 256, SMEM_CONV>>>(noise, nwp, out);
}

// round 7
// speedup vs baseline: 3.4514x; 1.7950x over previous
#include <cuda_runtime.h>
#include <cuda_fp16.h>
#include <cstdint>

// ---------------------------------------------------------------------------
// StyledLayer (sm_100 plain target): bilinear 2x up -> style -> modulated 3x3
// conv as FP16 mma.sync.m16n8k16 implicit GEMM (f32 accumulate) -> demod ->
// noise -> leaky_relu * sqrt(2).
// fp16 mantissa (11 bits) == tf32 mantissa, so accuracy matches the tf32
// round-6 run (rel_err 2.9e-4) while halving HMMA/LDSM instruction counts
// and all operand bytes.
// ---------------------------------------------------------------------------

#define BATCH 16
#define CIN   512
#define COUT  512
#define SDIM  512
#define HIN   32
#define WIN   32
#define NPIX  4096
#define KTOT  4608              // 9 * 512

#define LIN_SCALE  0.044194173824159216f
#define CONV_SCALE 0.014731391274719738f
#define ACT_GAIN   1.4142135623730951f
#define NEG_SLOPE  0.2f
#define DEMOD_EPS  1e-8f

// GEMM tiling: CTA 128(m) x 256(n), K-chunk = 32 halfs (64B row + 16B pad)
#define BM 128
#define BN 256
#define NCHUNK 144              // KTOT / 32
#define RB 80                   // bytes per smem row (64B data + 16B pad)
#define A_BYTES (BM * RB)       // 10240
#define B_BYTES (BN * RB)       // 20480
#define STAGE_BYTES (A_BYTES + B_BYTES)   // 30720
#define NSTAGE 3
#define SMEM_CONV (NSTAGE * STAGE_BYTES)  // 92160

// scratch
__device__ __half g_xt[BATCH * NPIX * CIN];  // [b][pix][ci], modulated, fp16
__device__ __half g_wK[COUT * KTOT];         // [cout][pos*512+ci], scaled, fp16
__device__ float  g_wsq[CIN * COUT];
__device__ float  g_s[BATCH * CIN];
__device__ float  g_demod[BATCH * COUT];

// ---------------------------------------------------------------------------
// PTX helpers
// ---------------------------------------------------------------------------
__device__ __forceinline__ uint32_t smem_u32(const void* p) {
    uint32_t a;
    asm("{ .reg .u64 t; cvta.to.shared.u64 t, %1; cvt.u32.u64 %0, t; }"
        : "=r"(a) : "l"(p));
    return a;
}

__device__ __forceinline__ void cp16(uint32_t dst, const void* src, int sz) {
    asm volatile("cp.async.cg.shared.global [%0], [%1], 16, %2;"
                 :: "r"(dst), "l"(src), "r"(sz));
}

#define CP_COMMIT() asm volatile("cp.async.commit_group;" ::: "memory")
#define CP_WAIT1()  asm volatile("cp.async.wait_group 1;" ::: "memory")
#define CP_WAIT0()  asm volatile("cp.async.wait_group 0;" ::: "memory")

__device__ __forceinline__ void ldsm4(uint32_t* r, uint32_t addr) {
    asm volatile("ldmatrix.sync.aligned.m8n8.x4.shared.b16 {%0,%1,%2,%3}, [%4];"
                 : "=r"(r[0]), "=r"(r[1]), "=r"(r[2]), "=r"(r[3]) : "r"(addr));
}

// m16n8k16 fp16, f32 accumulate
__device__ __forceinline__ void mma16(float* d, const uint32_t* a, const uint32_t* b) {
    asm volatile(
        "mma.sync.aligned.m16n8k16.row.col.f32.f16.f16.f32 "
        "{%0,%1,%2,%3}, {%4,%5,%6,%7}, {%8,%9}, {%0,%1,%2,%3};"
        : "+f"(d[0]), "+f"(d[1]), "+f"(d[2]), "+f"(d[3])
        : "r"(a[0]), "r"(a[1]), "r"(a[2]), "r"(a[3]), "r"(b[0]), "r"(b[1]));
}

// ---------------------------------------------------------------------------
// prep kernels
// ---------------------------------------------------------------------------
__global__ void style_k(const float* __restrict__ w,
                        const float* __restrict__ lin_w,
                        const float* __restrict__ lin_b) {
    int b = blockIdx.x;
    int c = threadIdx.x;
    __shared__ float ws[SDIM];
    ws[c] = w[b * SDIM + c];
    __syncthreads();
    const float* row = lin_w + (size_t)c * SDIM;
    float acc = 0.f;
#pragma unroll 8
    for (int i = 0; i < SDIM; i++) acc += ws[i] * row[i];
    g_s[b * CIN + c] = acc * LIN_SCALE + lin_b[c];
}

// g_wK[o][pos*512+ci] = half(conv_w[o][ci][pos] * CONV_SCALE)
__global__ void wk_k(const float* __restrict__ conv_w) {
    int idx = blockIdx.x * 256 + threadIdx.x;
    if (idx >= COUT * CIN) return;
    int ci = idx & 511;
    int o  = idx >> 9;
    const float* src = conv_w + ((size_t)o * CIN + ci) * 9;
    __half* dst = g_wK + (size_t)o * KTOT + ci;
#pragma unroll
    for (int p = 0; p < 9; p++)
        dst[p * 512] = __float2half(src[p] * CONV_SCALE);
}

__global__ void wsq_k(const float* __restrict__ conv_w) {
    int idx = blockIdx.x * 256 + threadIdx.x;
    if (idx >= COUT * CIN) return;
    int o = idx & 511;
    int i = idx >> 9;
    const float* src = conv_w + ((size_t)o * CIN + i) * 9;
    float sq = 0.f;
#pragma unroll
    for (int p = 0; p < 9; p++) {
        float v = src[p] * CONV_SCALE;
        sq += v * v;
    }
    g_wsq[(size_t)i * COUT + o] = sq;
}

// demod: grid (16,4) x 512 threads; 128 outs per block, 4 K-slices of 128
__global__ void demod_k() {
    __shared__ float s2[CIN];
    __shared__ float part[4][128];
    int b  = blockIdx.x;
    int og = blockIdx.y;
    int t  = threadIdx.x;
    int o  = og * 128 + (t & 127);
    int sl = t >> 7;

    float sv = g_s[b * CIN + t];
    s2[t] = sv * sv;
    __syncthreads();

    float acc = 0.f;
    int ci0 = sl * 128;
#pragma unroll 8
    for (int i = 0; i < 128; i++)
        acc += s2[ci0 + i] * g_wsq[(size_t)(ci0 + i) * COUT + o];
    part[sl][t & 127] = acc;
    __syncthreads();
    if (sl == 0) {
        float d = part[0][t] + part[1][t] + part[2][t] + part[3][t];
        g_demod[b * COUT + o] = rsqrtf(d + DEMOD_EPS);
    }
}

// ---------------------------------------------------------------------------
// upsample + modulate + transpose: g_xt[b][pix][ci] fp16
// ---------------------------------------------------------------------------
__global__ void __launch_bounds__(256) xt_k(const float* __restrict__ x) {
    extern __shared__ float sm[];          // [32][1025]
    int b  = blockIdx.x >> 4;
    int cb = blockIdx.x & 15;
    int ci0 = cb * 32;
    int tid = threadIdx.x;

    const float* xb = x + ((size_t)(b * CIN + ci0)) * (HIN * WIN);
#pragma unroll
    for (int i = 0; i < 32; i++)
        for (int j = tid; j < 1024; j += 256)
            sm[i * 1025 + j] = xb[(size_t)i * 1024 + j];
    __syncthreads();

    int c  = tid & 31;
    int pg = tid >> 5;
    float sv = g_s[b * CIN + ci0 + c];
    __half* dst = g_xt + (size_t)b * NPIX * CIN + ci0 + c;
    const float* row = sm + c * 1025;

    for (int e = 0; e < 512; e++) {
        int p  = pg + (e << 3);
        int py = p >> 6, px = p & 63;
        int fy = (py - 1) >> 1;
        int fx = (px - 1) >> 1;
        float ay = (py & 1) ? 0.25f : 0.75f;
        float ax = (px & 1) ? 0.25f : 0.75f;
        int y0 = max(fy, 0), y1 = min(fy + 1, HIN - 1);
        int x0 = max(fx, 0), x1 = min(fx + 1, WIN - 1);
        float v00 = row[y0 * WIN + x0];
        float v01 = row[y0 * WIN + x1];
        float v10 = row[y1 * WIN + x0];
        float v11 = row[y1 * WIN + x1];
        float val = (1.f - ay) * ((1.f - ax) * v00 + ax * v01)
                  +        ay  * ((1.f - ax) * v10 + ax * v11);
        dst[(size_t)p * CIN] = __float2half(sv * val);
    }
}

// ---------------------------------------------------------------------------
// conv: FP16 mma.sync.m16n8k16 implicit GEMM.
// CTA 128(m) x 256(n); K-chunks of 32 halfs (144 chunks over 9 positions).
// smem rows: 32 halfs data (64B) padded to 80B -> conflict-free ldmatrix.
// ---------------------------------------------------------------------------
__global__ void __launch_bounds__(256, 1)
conv_mma_k(const float* __restrict__ noise,
           const float* __restrict__ nwp,
           float* __restrict__ out) {
    extern __shared__ char smem[];
    uint32_t sb = smem_u32(smem);

    int tid  = threadIdx.x;
    int lane = tid & 31;
    int wid  = tid >> 5;
    int wm   = (wid & 1) * 64;          // warp m offset
    int wn   = (wid >> 1) * 64;         // warp n offset

    int b  = blockIdx.z;
    int m0 = blockIdx.y * BM;
    int n0 = blockIdx.x * BN;
    int py0 = n0 >> 6;                  // 4 rows of 64 pixels per CTA

    const __half* xtb = g_xt + (size_t)b * NPIX * CIN;

    // ---- cp.async mapping ----
    // A: rows of 64B = 4 x 16B; 512 chunk-writes over 256 threads (2 each)
    int am[2], ae[2];
    uint32_t adst[2];
#pragma unroll
    for (int e2 = 0; e2 < 2; e2++) {
        int idx = tid * 2 + e2;
        am[e2] = idx >> 2;              // 0..127
        ae[e2] = idx & 3;               // 0..3
        adst[e2] = am[e2] * RB + ae[e2] * 16;
    }
    // B: pixel n = tid; 4 x 16B = 32 halfs (full K-chunk row)
    int brow = tid >> 6;                // 0..3
    int bcol = tid & 63;
    uint32_t bdst0 = A_BYTES + tid * RB;

    // ---- ldmatrix offsets (canonical hgemm pattern) ----
    int g = lane >> 3, r = lane & 7;
    // A mats: {m0-7,k0},{m8-15,k0},{m0-7,k8},{m8-15,k8}
    uint32_t aoff = (uint32_t)((wm + (g & 1) * 8 + r) * RB + (g >> 1) * 16);
    // B mats: {n0-7,k0},{n0-7,k8},{n8-15,k0},{n8-15,k8}
    uint32_t boff = (uint32_t)(A_BYTES + (wn + (g >> 1) * 8 + r) * RB + (g & 1) * 16);

    float acc[4][8][4];
#pragma unroll
    for (int i = 0; i < 4; i++)
#pragma unroll
        for (int j = 0; j < 8; j++)
#pragma unroll
            for (int q = 0; q < 4; q++) acc[i][j][q] = 0.f;

    // ---- chunk loader (K-chunk = 32 halfs) ----
    auto load_chunk = [&](int c, int st) {
        int pos = c >> 4;               // 16 chunks of 32 per position
        int ci0 = (c & 15) << 5;        // 0,32,...,480
        int dy = pos / 3 - 1, dx = pos % 3 - 1;
        int kbase = pos * 512 + ci0;
        uint32_t stb = sb + st * STAGE_BYTES;
#pragma unroll
        for (int e2 = 0; e2 < 2; e2++) {
            const __half* src = g_wK + (size_t)(m0 + am[e2]) * KTOT + kbase + ae[e2] * 8;
            cp16(stb + adst[e2], src, 16);
        }
        int py = py0 + brow + dy;
        int px = bcol + dx;
        bool v = ((unsigned)py < 64u) && ((unsigned)px < 64u);
        const __half* bsrc = xtb + ((size_t)(v ? (py * 64 + px) : 0) * CIN) + ci0;
        int sz = v ? 16 : 0;
#pragma unroll
        for (int e = 0; e < 4; e++)
            cp16(stb + bdst0 + e * 16, bsrc + e * 8, sz);
        CP_COMMIT();
    };

    load_chunk(0, 0);
    load_chunk(1, 1);

    for (int c = 0; c < NCHUNK; c++) {
        int s = c % NSTAGE;
        if (c + 1 < NCHUNK) { CP_WAIT1(); } else { CP_WAIT0(); }
        __syncthreads();

        if (c + 2 < NCHUNK) load_chunk(c + 2, (c + 2) % NSTAGE);

        uint32_t stb = sb + s * STAGE_BYTES;
#pragma unroll
        for (int ks = 0; ks < 2; ks++) {       // two k16 steps per chunk
            uint32_t af[4][4], bf[4][4];
#pragma unroll
            for (int mt = 0; mt < 4; mt++)
                ldsm4(af[mt], stb + aoff + mt * (16 * RB) + ks * 32);
#pragma unroll
            for (int j = 0; j < 4; j++)
                ldsm4(bf[j], stb + boff + j * (16 * RB) + ks * 32);
#pragma unroll
            for (int mt = 0; mt < 4; mt++)
#pragma unroll
                for (int nt = 0; nt < 8; nt++)
                    mma16(acc[mt][nt], af[mt], &bf[nt >> 1][(nt & 1) * 2]);
        }
    }

    // ---- epilogue: demod + noise + lrelu*gain, float2 stores ----
    float nw = *nwp;
    const float* nb = noise + (size_t)b * NPIX;
#pragma unroll
    for (int mt = 0; mt < 4; mt++) {
        int rbase = m0 + wm + mt * 16 + (lane >> 2);
#pragma unroll
        for (int half = 0; half < 2; half++) {
            int cout = rbase + half * 8;
            float dm = g_demod[b * COUT + cout];
            float* orow = out + ((size_t)(b * COUT + cout)) * NPIX;
#pragma unroll
            for (int nt = 0; nt < 8; nt++) {
                int pix = n0 + wn + nt * 8 + 2 * (lane & 3);
                float v0 = acc[mt][nt][half * 2 + 0] * dm + nw * nb[pix];
                float v1 = acc[mt][nt][half * 2 + 1] * dm + nw * nb[pix + 1];
                v0 = (v0 >= 0.f ? v0 : NEG_SLOPE * v0) * ACT_GAIN;
                v1 = (v1 >= 0.f ? v1 : NEG_SLOPE * v1) * ACT_GAIN;
                float2 o2 = make_float2(v0, v1);
                *(float2*)(orow + pix) = o2;
            }
        }
    }
}

// ---------------------------------------------------------------------------
extern "C" void kernel_launch(void* const* d_in, const int* in_sizes, int n_in,
                              void* d_out, int out_size) {
    const float* x      = (const float*)d_in[0];
    const float* w      = (const float*)d_in[1];
    const float* noise  = (const float*)d_in[2];
    const float* lin_w  = (const float*)d_in[3];
    const float* lin_b  = (const float*)d_in[4];
    const float* conv_w = (const float*)d_in[5];
    const float* nwp    = (const float*)d_in[6];
    float* out = (float*)d_out;

    cudaFuncSetAttribute(xt_k, cudaFuncAttributeMaxDynamicSharedMemorySize, 32 * 1025 * 4);
    cudaFuncSetAttribute(conv_mma_k, cudaFuncAttributeMaxDynamicSharedMemorySize, SMEM_CONV);

    style_k<<<BATCH, 512>>>(w, lin_w, lin_b);
    wk_k<<<(COUT * CIN + 255) / 256, 256>>>(conv_w);
    wsq_k<<<(COUT * CIN + 255) / 256, 256>>>(conv_w);
    demod_k<<<dim3(BATCH, 4), 512>>>();
    xt_k<<<BATCH * 16, 256, 32 * 1025 * 4>>>(x);

    dim3 grid(NPIX / BN, COUT / BM, BATCH);   // (16, 4, 16)
    conv_mma_k<<<grid, 256, SMEM_CONV>>>(noise, nwp, out);
}

// round 8
// speedup vs baseline: 4.3433x; 1.2584x over previous
#include <cuda_runtime.h>
#include <cuda_fp16.h>
#include <cstdint>

// ---------------------------------------------------------------------------
// StyledLayer (sm_100 plain target): bilinear 2x up -> style -> modulated 3x3
// conv as FP16 mma.sync.m16n8k16 implicit GEMM (f32 accumulate) -> demod ->
// noise -> leaky_relu * sqrt(2).
// Round 8: 512-thread conv CTA (16 warps, 32x64 warp tile) -> 4 warps/SMSP
// to test the latency-bound hypothesis on the fallback HMMA path.
// ---------------------------------------------------------------------------

#define BATCH 16
#define CIN   512
#define COUT  512
#define SDIM  512
#define HIN   32
#define WIN   32
#define NPIX  4096
#define KTOT  4608              // 9 * 512

#define LIN_SCALE  0.044194173824159216f
#define CONV_SCALE 0.014731391274719738f
#define ACT_GAIN   1.4142135623730951f
#define NEG_SLOPE  0.2f
#define DEMOD_EPS  1e-8f

// GEMM tiling: CTA 128(m) x 256(n), K-chunk = 32 halfs (64B row + 16B pad)
#define BM 128
#define BN 256
#define NCHUNK 144              // KTOT / 32
#define RB 80                   // bytes per smem row (64B data + 16B pad)
#define A_BYTES (BM * RB)       // 10240
#define B_BYTES (BN * RB)       // 20480
#define STAGE_BYTES (A_BYTES + B_BYTES)   // 30720
#define NSTAGE 3
#define SMEM_CONV (NSTAGE * STAGE_BYTES)  // 92160

// scratch
__device__ __half g_xt[BATCH * NPIX * CIN];  // [b][pix][ci], modulated, fp16
__device__ __half g_wK[COUT * KTOT];         // [cout][pos*512+ci], scaled, fp16
__device__ float  g_wsq[CIN * COUT];
__device__ float  g_s[BATCH * CIN];
__device__ float  g_demod[BATCH * COUT];

// ---------------------------------------------------------------------------
// PTX helpers
// ---------------------------------------------------------------------------
__device__ __forceinline__ uint32_t smem_u32(const void* p) {
    uint32_t a;
    asm("{ .reg .u64 t; cvta.to.shared.u64 t, %1; cvt.u32.u64 %0, t; }"
        : "=r"(a) : "l"(p));
    return a;
}

__device__ __forceinline__ void cp16(uint32_t dst, const void* src, int sz) {
    asm volatile("cp.async.cg.shared.global [%0], [%1], 16, %2;"
                 :: "r"(dst), "l"(src), "r"(sz));
}

#define CP_COMMIT() asm volatile("cp.async.commit_group;" ::: "memory")
#define CP_WAIT1()  asm volatile("cp.async.wait_group 1;" ::: "memory")
#define CP_WAIT0()  asm volatile("cp.async.wait_group 0;" ::: "memory")

__device__ __forceinline__ void ldsm4(uint32_t* r, uint32_t addr) {
    asm volatile("ldmatrix.sync.aligned.m8n8.x4.shared.b16 {%0,%1,%2,%3}, [%4];"
                 : "=r"(r[0]), "=r"(r[1]), "=r"(r[2]), "=r"(r[3]) : "r"(addr));
}

// m16n8k16 fp16, f32 accumulate
__device__ __forceinline__ void mma16(float* d, const uint32_t* a, const uint32_t* b) {
    asm volatile(
        "mma.sync.aligned.m16n8k16.row.col.f32.f16.f16.f32 "
        "{%0,%1,%2,%3}, {%4,%5,%6,%7}, {%8,%9}, {%0,%1,%2,%3};"
        : "+f"(d[0]), "+f"(d[1]), "+f"(d[2]), "+f"(d[3])
        : "r"(a[0]), "r"(a[1]), "r"(a[2]), "r"(a[3]), "r"(b[0]), "r"(b[1]));
}

// ---------------------------------------------------------------------------
// prep kernels
// ---------------------------------------------------------------------------
__global__ void style_k(const float* __restrict__ w,
                        const float* __restrict__ lin_w,
                        const float* __restrict__ lin_b) {
    int b = blockIdx.x;
    int c = threadIdx.x;
    __shared__ float ws[SDIM];
    ws[c] = w[b * SDIM + c];
    __syncthreads();
    const float* row = lin_w + (size_t)c * SDIM;
    float acc = 0.f;
#pragma unroll 8
    for (int i = 0; i < SDIM; i++) acc += ws[i] * row[i];
    g_s[b * CIN + c] = acc * LIN_SCALE + lin_b[c];
}

// g_wK[o][pos*512+ci] = half(conv_w[o][ci][pos] * CONV_SCALE)
__global__ void wk_k(const float* __restrict__ conv_w) {
    int idx = blockIdx.x * 256 + threadIdx.x;
    if (idx >= COUT * CIN) return;
    int ci = idx & 511;
    int o  = idx >> 9;
    const float* src = conv_w + ((size_t)o * CIN + ci) * 9;
    __half* dst = g_wK + (size_t)o * KTOT + ci;
#pragma unroll
    for (int p = 0; p < 9; p++)
        dst[p * 512] = __float2half(src[p] * CONV_SCALE);
}

__global__ void wsq_k(const float* __restrict__ conv_w) {
    int idx = blockIdx.x * 256 + threadIdx.x;
    if (idx >= COUT * CIN) return;
    int o = idx & 511;
    int i = idx >> 9;
    const float* src = conv_w + ((size_t)o * CIN + i) * 9;
    float sq = 0.f;
#pragma unroll
    for (int p = 0; p < 9; p++) {
        float v = src[p] * CONV_SCALE;
        sq += v * v;
    }
    g_wsq[(size_t)i * COUT + o] = sq;
}

// demod: grid (16,4) x 512 threads; 128 outs per block, 4 K-slices of 128
__global__ void demod_k() {
    __shared__ float s2[CIN];
    __shared__ float part[4][128];
    int b  = blockIdx.x;
    int og = blockIdx.y;
    int t  = threadIdx.x;
    int o  = og * 128 + (t & 127);
    int sl = t >> 7;

    float sv = g_s[b * CIN + t];
    s2[t] = sv * sv;
    __syncthreads();

    float acc = 0.f;
    int ci0 = sl * 128;
#pragma unroll 8
    for (int i = 0; i < 128; i++)
        acc += s2[ci0 + i] * g_wsq[(size_t)(ci0 + i) * COUT + o];
    part[sl][t & 127] = acc;
    __syncthreads();
    if (sl == 0) {
        float d = part[0][t] + part[1][t] + part[2][t] + part[3][t];
        g_demod[b * COUT + o] = rsqrtf(d + DEMOD_EPS);
    }
}

// ---------------------------------------------------------------------------
// upsample + modulate + transpose: g_xt[b][pix][ci] fp16
// ---------------------------------------------------------------------------
__global__ void __launch_bounds__(256) xt_k(const float* __restrict__ x) {
    extern __shared__ float sm[];          // [32][1025]
    int b  = blockIdx.x >> 4;
    int cb = blockIdx.x & 15;
    int ci0 = cb * 32;
    int tid = threadIdx.x;

    const float* xb = x + ((size_t)(b * CIN + ci0)) * (HIN * WIN);
#pragma unroll
    for (int i = 0; i < 32; i++)
        for (int j = tid; j < 1024; j += 256)
            sm[i * 1025 + j] = xb[(size_t)i * 1024 + j];
    __syncthreads();

    int c  = tid & 31;
    int pg = tid >> 5;
    float sv = g_s[b * CIN + ci0 + c];
    __half* dst = g_xt + (size_t)b * NPIX * CIN + ci0 + c;
    const float* row = sm + c * 1025;

    for (int e = 0; e < 512; e++) {
        int p  = pg + (e << 3);
        int py = p >> 6, px = p & 63;
        int fy = (py - 1) >> 1;
        int fx = (px - 1) >> 1;
        float ay = (py & 1) ? 0.25f : 0.75f;
        float ax = (px & 1) ? 0.25f : 0.75f;
        int y0 = max(fy, 0), y1 = min(fy + 1, HIN - 1);
        int x0 = max(fx, 0), x1 = min(fx + 1, WIN - 1);
        float v00 = row[y0 * WIN + x0];
        float v01 = row[y0 * WIN + x1];
        float v10 = row[y1 * WIN + x0];
        float v11 = row[y1 * WIN + x1];
        float val = (1.f - ay) * ((1.f - ax) * v00 + ax * v01)
                  +        ay  * ((1.f - ax) * v10 + ax * v11);
        dst[(size_t)p * CIN] = __float2half(sv * val);
    }
}

// ---------------------------------------------------------------------------
// conv: FP16 mma.sync.m16n8k16 implicit GEMM.
// CTA 128(m) x 256(n), 512 threads, 16 warps, warp tile 32x64.
// K-chunks of 32 halfs (144 chunks over 9 positions), 3-stage cp.async.
// ---------------------------------------------------------------------------
__global__ void __launch_bounds__(512, 1)
conv_mma_k(const float* __restrict__ noise,
           const float* __restrict__ nwp,
           float* __restrict__ out) {
    extern __shared__ char smem[];
    uint32_t sb = smem_u32(smem);

    int tid  = threadIdx.x;
    int lane = tid & 31;
    int wid  = tid >> 5;
    int wm   = (wid & 3) * 32;          // warp m offset (4 m-warps)
    int wn   = (wid >> 2) * 64;         // warp n offset (4 n-warps)

    int b  = blockIdx.z;
    int m0 = blockIdx.y * BM;
    int n0 = blockIdx.x * BN;
    int py0 = n0 >> 6;                  // 4 rows of 64 pixels per CTA

    const __half* xtb = g_xt + (size_t)b * NPIX * CIN;

    // ---- cp.async mapping (512 threads) ----
    // A: 128 rows x 4 chunks of 16B = 512 -> 1 per thread
    int am = tid >> 2, ae = tid & 3;
    uint32_t adst = am * RB + ae * 16;
    // B: 256 rows x 4 chunks = 1024 -> 2 per thread (one half-row each)
    int bn    = tid >> 1;               // pixel row 0..255
    int bhalf = tid & 1;                // which 32B half of the 64B row
    int brow = bn >> 6, bcol = bn & 63;
    uint32_t bdst = A_BYTES + bn * RB + bhalf * 32;

    // ---- ldmatrix offsets ----
    int g = lane >> 3, r = lane & 7;
    uint32_t aoff = (uint32_t)((wm + (g & 1) * 8 + r) * RB + (g >> 1) * 16);
    uint32_t boff = (uint32_t)(A_BYTES + (wn + (g >> 1) * 8 + r) * RB + (g & 1) * 16);

    float acc[2][8][4];
#pragma unroll
    for (int i = 0; i < 2; i++)
#pragma unroll
        for (int j = 0; j < 8; j++)
#pragma unroll
            for (int q = 0; q < 4; q++) acc[i][j][q] = 0.f;

    // ---- chunk loader (K-chunk = 32 halfs) ----
    auto load_chunk = [&](int c, int st) {
        int pos = c >> 4;               // 16 chunks of 32 per position
        int ci0 = (c & 15) << 5;        // 0,32,...,480
        int dy = pos / 3 - 1, dx = pos % 3 - 1;
        int kbase = pos * 512 + ci0;
        uint32_t stb = sb + st * STAGE_BYTES;

        const __half* asrc = g_wK + (size_t)(m0 + am) * KTOT + kbase + ae * 8;
        cp16(stb + adst, asrc, 16);

        int py = py0 + brow + dy;
        int px = bcol + dx;
        bool v = ((unsigned)py < 64u) && ((unsigned)px < 64u);
        const __half* bsrc = xtb + ((size_t)(v ? (py * 64 + px) : 0) * CIN)
                           + ci0 + bhalf * 16;
        int sz = v ? 16 : 0;
        cp16(stb + bdst,      bsrc,     sz);
        cp16(stb + bdst + 16, bsrc + 8, sz);
        CP_COMMIT();
    };

    load_chunk(0, 0);
    load_chunk(1, 1);

    for (int c = 0; c < NCHUNK; c++) {
        int s = c % NSTAGE;
        if (c + 1 < NCHUNK) { CP_WAIT1(); } else { CP_WAIT0(); }
        __syncthreads();

        if (c + 2 < NCHUNK) load_chunk(c + 2, (c + 2) % NSTAGE);

        uint32_t stb = sb + s * STAGE_BYTES;
#pragma unroll
        for (int ks = 0; ks < 2; ks++) {       // two k16 steps per chunk
            uint32_t af[2][4], bf[4][4];
#pragma unroll
            for (int mt = 0; mt < 2; mt++)
                ldsm4(af[mt], stb + aoff + mt * (16 * RB) + ks * 32);
#pragma unroll
            for (int j = 0; j < 4; j++)
                ldsm4(bf[j], stb + boff + j * (16 * RB) + ks * 32);
#pragma unroll
            for (int mt = 0; mt < 2; mt++)
#pragma unroll
                for (int nt = 0; nt < 8; nt++)
                    mma16(acc[mt][nt], af[mt], &bf[nt >> 1][(nt & 1) * 2]);
        }
    }

    // ---- epilogue: demod + noise + lrelu*gain, float2 stores ----
    float nw = *nwp;
    const float* nb = noise + (size_t)b * NPIX;
#pragma unroll
    for (int mt = 0; mt < 2; mt++) {
        int rbase = m0 + wm + mt * 16 + (lane >> 2);
#pragma unroll
        for (int half = 0; half < 2; half++) {
            int cout = rbase + half * 8;
            float dm = g_demod[b * COUT + cout];
            float* orow = out + ((size_t)(b * COUT + cout)) * NPIX;
#pragma unroll
            for (int nt = 0; nt < 8; nt++) {
                int pix = n0 + wn + nt * 8 + 2 * (lane & 3);
                float v0 = acc[mt][nt][half * 2 + 0] * dm + nw * nb[pix];
                float v1 = acc[mt][nt][half * 2 + 1] * dm + nw * nb[pix + 1];
                v0 = (v0 >= 0.f ? v0 : NEG_SLOPE * v0) * ACT_GAIN;
                v1 = (v1 >= 0.f ? v1 : NEG_SLOPE * v1) * ACT_GAIN;
                float2 o2 = make_float2(v0, v1);
                *(float2*)(orow + pix) = o2;
            }
        }
    }
}

// ---------------------------------------------------------------------------
extern "C" void kernel_launch(void* const* d_in, const int* in_sizes, int n_in,
                              void* d_out, int out_size) {
    const float* x      = (const float*)d_in[0];
    const float* w      = (const float*)d_in[1];
    const float* noise  = (const float*)d_in[2];
    const float* lin_w  = (const float*)d_in[3];
    const float* lin_b  = (const float*)d_in[4];
    const float* conv_w = (const float*)d_in[5];
    const float* nwp    = (const float*)d_in[6];
    float* out = (float*)d_out;

    cudaFuncSetAttribute(xt_k, cudaFuncAttributeMaxDynamicSharedMemorySize, 32 * 1025 * 4);
    cudaFuncSetAttribute(conv_mma_k, cudaFuncAttributeMaxDynamicSharedMemorySize, SMEM_CONV);

    style_k<<<BATCH, 512>>>(w, lin_w, lin_b);
    wk_k<<<(COUT * CIN + 255) / 256, 256>>>(conv_w);
    wsq_k<<<(COUT * CIN + 255) / 256, 256>>>(conv_w);
    demod_k<<<dim3(BATCH, 4), 512>>>();
    xt_k<<<BATCH * 16, 256, 32 * 1025 * 4>>>(x);

    dim3 grid(NPIX / BN, COUT / BM, BATCH);   // (16, 4, 16)
    conv_mma_k<<<grid, 512, SMEM_CONV>>>(noise, nwp, out);
}